// round 1
// baseline (speedup 1.0000x reference)
#include <cuda_runtime.h>

// QKVAttention: qkv (4, 1536, 2048) fp32 -> out (4, 512, 2048) fp32
// 8 heads per batch, ch=64, T=2048. softmax((q*s)·(k*s)) @ v, s = ch^-0.25.
// Flash-attention style, fp32 SIMT baseline.

#define TT   2048
#define DD   64
#define WW   1536
#define BQ   64
#define BK   64
#define NKT  (TT / BK)
#define SP   68                       // padded row stride (floats), 16B-aligned
#define SMEM_BYTES (4 * DD * SP * 4)  // sQ + sK + sV + sS = 69632 B

__global__ __launch_bounds__(256, 2)
void qkv_attn_kernel(const float* __restrict__ qkv, float* __restrict__ out)
{
    const int tile = blockIdx.x;      // query tile 0..31
    const int bh   = blockIdx.y;      // head 0..31
    const int b    = bh >> 3;
    const int h    = bh & 7;
    const int tid  = threadIdx.x;

    extern __shared__ float sm[];
    float* sQ = sm;                   // [DD][SP]  Q[ch][q]  (pre-scaled by 0.125)
    float* sK = sQ + DD * SP;         // [DD][SP]  K[ch][s]
    float* sV = sK + DD * SP;         // [BK][SP]  V[s][ch]  (transposed)
    float* sS = sV + BK * SP;         // [BQ][SP]  scores / probabilities

    const size_t base = (size_t)b * (WW * TT) + (size_t)h * (DD * TT);
    const float* Qg = qkv + base;
    const float* Kg = qkv + base + (size_t)512  * TT;
    const float* Vg = qkv + base + (size_t)1024 * TT;

    // ---- load mapping: thread -> (channel row, 16-wide column chunk)
    const int lc = tid >> 2;          // 0..63
    const int ls = (tid & 3) << 4;    // 0,16,32,48

    // ---- load Q tile once, fold in scale^2 = 1/8
    {
        const int q0 = tile * BQ;
        #pragma unroll
        for (int j = 0; j < 4; j++) {
            float4 v = *(const float4*)(Qg + (size_t)lc * TT + q0 + ls + j * 4);
            v.x *= 0.125f; v.y *= 0.125f; v.z *= 0.125f; v.w *= 0.125f;
            *(float4*)(sQ + lc * SP + ls + j * 4) = v;
        }
    }

    // ---- phase A mapping: 16x16 thread grid, 4x4 S subtile each
    const int tq = (tid & 15) << 2;
    const int ts = (tid >> 4) << 2;
    // ---- phase B mapping: quad of threads per query, 16 channels each
    const int q  = tid >> 2;          // 0..63
    const int g  = (tid & 3) << 4;    // 0,16,32,48

    float acc[16];
    #pragma unroll
    for (int i = 0; i < 16; i++) acc[i] = 0.f;
    float mrun = -1e30f, lrun = 0.f;

    for (int kt = 0; kt < NKT; kt++) {
        const int s0 = kt * BK;

        __syncthreads();  // prev tile fully consumed; sQ ready on first iter

        // ---- load K tile (row-major) and V tile (transposed) into smem
        #pragma unroll
        for (int j = 0; j < 4; j++) {
            float4 kv = *(const float4*)(Kg + (size_t)lc * TT + s0 + ls + j * 4);
            *(float4*)(sK + lc * SP + ls + j * 4) = kv;
            float4 vv = *(const float4*)(Vg + (size_t)lc * TT + s0 + ls + j * 4);
            sV[(ls + j * 4 + 0) * SP + lc] = vv.x;
            sV[(ls + j * 4 + 1) * SP + lc] = vv.y;
            sV[(ls + j * 4 + 2) * SP + lc] = vv.z;
            sV[(ls + j * 4 + 3) * SP + lc] = vv.w;
        }
        __syncthreads();

        // ---- phase A: S = Q^T K (64x64), 4x4 per thread
        float cc[4][4];
        #pragma unroll
        for (int i = 0; i < 4; i++)
            #pragma unroll
            for (int j = 0; j < 4; j++) cc[i][j] = 0.f;

        #pragma unroll 8
        for (int ch = 0; ch < DD; ch++) {
            const float4 qa = *(const float4*)(sQ + ch * SP + tq);
            const float4 kb = *(const float4*)(sK + ch * SP + ts);
            const float qv[4] = {qa.x, qa.y, qa.z, qa.w};
            const float kv[4] = {kb.x, kb.y, kb.z, kb.w};
            #pragma unroll
            for (int i = 0; i < 4; i++)
                #pragma unroll
                for (int j = 0; j < 4; j++)
                    cc[i][j] = fmaf(qv[i], kv[j], cc[i][j]);
        }
        #pragma unroll
        for (int i = 0; i < 4; i++)
            *(float4*)(sS + (tq + i) * SP + ts) =
                make_float4(cc[i][0], cc[i][1], cc[i][2], cc[i][3]);
        __syncthreads();

        // ---- phase B: online softmax (quad owns one query row)
        float p[16];
        #pragma unroll
        for (int j = 0; j < 16; j += 4) {
            const float4 sv = *(const float4*)(sS + q * SP + g + j);
            p[j] = sv.x; p[j + 1] = sv.y; p[j + 2] = sv.z; p[j + 3] = sv.w;
        }
        float mloc = -1e30f;
        #pragma unroll
        for (int j = 0; j < 16; j++) mloc = fmaxf(mloc, p[j]);
        mloc = fmaxf(mloc, __shfl_xor_sync(0xffffffffu, mloc, 1));
        mloc = fmaxf(mloc, __shfl_xor_sync(0xffffffffu, mloc, 2));

        const float mnew = fmaxf(mrun, mloc);
        const float corr = __expf(mrun - mnew);
        mrun = mnew;

        float lsum = 0.f;
        #pragma unroll
        for (int j = 0; j < 16; j++) { p[j] = __expf(p[j] - mnew); lsum += p[j]; }
        lsum += __shfl_xor_sync(0xffffffffu, lsum, 1);
        lsum += __shfl_xor_sync(0xffffffffu, lsum, 2);
        lrun = lrun * corr + lsum;

        #pragma unroll
        for (int j = 0; j < 16; j++) acc[j] *= corr;

        // write probabilities back (quad-local: same warp -> syncwarp suffices)
        #pragma unroll
        for (int j = 0; j < 16; j += 4)
            *(float4*)(sS + q * SP + g + j) =
                make_float4(p[j], p[j + 1], p[j + 2], p[j + 3]);
        __syncwarp();

        // ---- PV: acc[ch] += sum_s P[q][s] * V[s][ch]
        #pragma unroll 4
        for (int s = 0; s < BK; s++) {
            const float pw = sS[q * SP + s];
            const float4 v0 = *(const float4*)(sV + s * SP + g);
            const float4 v1 = *(const float4*)(sV + s * SP + g + 4);
            const float4 v2 = *(const float4*)(sV + s * SP + g + 8);
            const float4 v3 = *(const float4*)(sV + s * SP + g + 12);
            acc[0]  = fmaf(pw, v0.x, acc[0]);  acc[1]  = fmaf(pw, v0.y, acc[1]);
            acc[2]  = fmaf(pw, v0.z, acc[2]);  acc[3]  = fmaf(pw, v0.w, acc[3]);
            acc[4]  = fmaf(pw, v1.x, acc[4]);  acc[5]  = fmaf(pw, v1.y, acc[5]);
            acc[6]  = fmaf(pw, v1.z, acc[6]);  acc[7]  = fmaf(pw, v1.w, acc[7]);
            acc[8]  = fmaf(pw, v2.x, acc[8]);  acc[9]  = fmaf(pw, v2.y, acc[9]);
            acc[10] = fmaf(pw, v2.z, acc[10]); acc[11] = fmaf(pw, v2.w, acc[11]);
            acc[12] = fmaf(pw, v3.x, acc[12]); acc[13] = fmaf(pw, v3.y, acc[13]);
            acc[14] = fmaf(pw, v3.z, acc[14]); acc[15] = fmaf(pw, v3.w, acc[15]);
        }
    }

    // ---- epilogue: normalize and write out[b][h*64+ch][t]
    const float inv = 1.0f / lrun;
    const int   qg  = tile * BQ + q;
    float* ob = out + (size_t)b * (512 * TT) + (size_t)(h * DD + g) * TT + qg;
    #pragma unroll
    for (int j = 0; j < 16; j++)
        ob[(size_t)j * TT] = acc[j] * inv;
}

extern "C" void kernel_launch(void* const* d_in, const int* in_sizes, int n_in,
                              void* d_out, int out_size)
{
    const float* qkv = (const float*)d_in[0];
    float* out = (float*)d_out;

    cudaFuncSetAttribute(qkv_attn_kernel,
                         cudaFuncAttributeMaxDynamicSharedMemorySize, SMEM_BYTES);

    dim3 grid(TT / BQ, 32);   // 32 query tiles x 32 heads
    qkv_attn_kernel<<<grid, 256, SMEM_BYTES>>>(qkv, out);
}